// round 1
// baseline (speedup 1.0000x reference)
#include <cuda_runtime.h>
#include <cuda_bf16.h>

// PositionalEncoding2D:
//   pe[i, b, 2p]   = sin(x[i,b,0] * dt[p])
//   pe[i, b, 2p+1] = cos(x[i,b,1] * dt[p])
//   dt[p] = exp(p * -ln(1e4)/256),  p in [0,256)
//
// Input : x   [2048, 32, 2] fp32  (row = (i,b), 2 floats per row)
// Output: pe  [2048, 32, 512] fp32 = 128 MB  -> store-bandwidth bound.
//
// One thread produces one float4 = pairs (p, p+1). 128 threads/row.

#define NUM_ROWS   (2048 * 32)      // 65536
#define QUADS_PER_ROW 128           // 512 floats / 4
#define TOTAL_QUADS (NUM_ROWS * QUADS_PER_ROW)

__global__ __launch_bounds__(256)
void pe2d_kernel(const float* __restrict__ x, float* __restrict__ out) {
    const int tid = blockIdx.x * 256 + threadIdx.x;   // grid sized exactly
    const int row = tid >> 7;        // / QUADS_PER_ROW
    const int t   = tid & 127;       // quad index within row

    // Per-row coords (broadcast across the 128 threads of the row; L1 hit)
    const float2 xy = __ldg(reinterpret_cast<const float2*>(x) + row);

    // dt[p] = exp(p * c), c = -ln(1e4)/256
    const float c = -9.210340371976184f / 256.0f;
    const float r = 0.96466168f;     // exp(c) = 10000^(-1/256)
    const int p = t << 1;            // pair base: 2t
    const float dt0 = __expf((float)p * c);   // 1 MUFU.EX2
    const float dt1 = dt0 * r;                // neighbor by recurrence (1 FMUL)

    float4 o;
    o.x = __sinf(xy.x * dt0);
    o.y = __cosf(xy.y * dt0);
    o.z = __sinf(xy.x * dt1);
    o.w = __cosf(xy.y * dt1);

    reinterpret_cast<float4*>(out)[tid] = o;   // coalesced 16B store
}

extern "C" void kernel_launch(void* const* d_in, const int* in_sizes, int n_in,
                              void* d_out, int out_size) {
    const float* x = (const float*)d_in[0];
    float* out = (float*)d_out;
    const int threads = 256;
    const int blocks = TOTAL_QUADS / threads;   // 8388608/256 = 32768
    pe2d_kernel<<<blocks, threads>>>(x, out);
}

// round 2
// speedup vs baseline: 1.3831x; 1.3831x over previous
#include <cuda_runtime.h>
#include <cuda_bf16.h>

// PositionalEncoding2D:
//   pe[i, b, 2p]   = sin(x[i,b,0] * dt[p])
//   pe[i, b, 2p+1] = cos(x[i,b,1] * dt[p])
//   dt[p] = exp(p * -ln(1e4)/256),  p in [0,256)
//
// Input : x  [65536 rows][2] fp32;  Output: [65536 rows][512] fp32 = 128 MB.
// Store-bandwidth bound; goal is to keep enough STG.128s in flight to reach
// the LTS cap.
//
// Layout: one warp per row. Lane t handles quads {t, t+32, t+64, t+96}.
// dt recurrence: quad step of +32 multiplies dt by 10000^(-64/256) = 0.1
// exactly, so one __expf + FMULs covers all 8 frequencies per thread.
// 4 independent coalesced 512B stores per warp iteration -> MLP=4.

#define NUM_ROWS (2048 * 32)   // 65536

__global__ __launch_bounds__(256)
void pe2d_kernel(const float* __restrict__ x, float4* __restrict__ out) {
    const int warp = (blockIdx.x * 256 + threadIdx.x) >> 5;  // row index
    const int lane = threadIdx.x & 31;

    // Per-row coords (uniform within warp -> broadcast LDG.64)
    const float2 xy = __ldg(reinterpret_cast<const float2*>(x) + warp);

    // dt for quad t: exp(2t * C), C = -ln(1e4)/256
    const float twoC = -9.210340371976184f / 128.0f;       // 2C
    const float r    = 0.9646616199111993f;                // 1e4^(-1/256): pair step
    float d0 = __expf((float)lane * twoC);                 // quad t
    float d1 = d0 * 0.1f;                                  // quad t+32
    float d2 = d1 * 0.1f;                                  // quad t+64
    float d3 = d2 * 0.1f;                                  // quad t+96

    float4* o = out + warp * 128 + lane;

    float4 v0, v1, v2, v3;
    v0.x = __sinf(xy.x * d0);  v0.y = __cosf(xy.y * d0);
    v0.z = __sinf(xy.x * (d0 * r));  v0.w = __cosf(xy.y * (d0 * r));
    v1.x = __sinf(xy.x * d1);  v1.y = __cosf(xy.y * d1);
    v1.z = __sinf(xy.x * (d1 * r));  v1.w = __cosf(xy.y * (d1 * r));
    v2.x = __sinf(xy.x * d2);  v2.y = __cosf(xy.y * d2);
    v2.z = __sinf(xy.x * (d2 * r));  v2.w = __cosf(xy.y * (d2 * r));
    v3.x = __sinf(xy.x * d3);  v3.y = __cosf(xy.y * d3);
    v3.z = __sinf(xy.x * (d3 * r));  v3.w = __cosf(xy.y * (d3 * r));

    o[0]  = v0;
    o[32] = v1;
    o[64] = v2;
    o[96] = v3;
}

extern "C" void kernel_launch(void* const* d_in, const int* in_sizes, int n_in,
                              void* d_out, int out_size) {
    const float* x = (const float*)d_in[0];
    float4* out = (float4*)d_out;
    // 65536 rows, 1 warp/row, 8 warps/block -> 8192 blocks
    pe2d_kernel<<<NUM_ROWS / 8, 256>>>(x, out);
}